// round 3
// baseline (speedup 1.0000x reference)
#include <cuda_runtime.h>
#include <math.h>

#define BATCH 16384
#define NNODES 200000
#define NK 16
#define EMB 256
#define NH 2
#define NA 64
#define HDIM 128
#define PROJ 128   // NH*NA

// ---------------- device scratch (static, allowed) ----------------
__device__ float g_P[(size_t)NNODES * PROJ];     // neighbor projections  (~102 MB)
__device__ float g_C[(size_t)BATCH * EMB];       // gathered centers
__device__ float g_CP[(size_t)BATCH * PROJ];     // center projections (+b1)
__device__ float g_G[(size_t)BATCH * EMB];       // gate pre-activations
__device__ float g_comb[(size_t)BATCH * EMB];    // combined (pre out-proj)
__device__ float g_Wc[EMB * PROJ];               // W1 center half, [e][h*64+a]
__device__ float g_Wnb[EMB * PROJ];              // W1 neighbor half
__device__ float g_Wg[NH * HDIM * HDIM];         // gate_W transposed: [h][d][e]
__device__ float g_WoutT[EMB * EMB];             // out_W transposed: [d][e]

// ---------------- weight repacking ----------------
__global__ void prepack_kernel(const float* __restrict__ W1,
                               const float* __restrict__ gateW,
                               const float* __restrict__ outW) {
    int total = EMB * PROJ * 2 + NH * HDIM * HDIM + EMB * EMB;
    for (int i = blockIdx.x * blockDim.x + threadIdx.x; i < total;
         i += gridDim.x * blockDim.x) {
        int t = i;
        if (t < EMB * PROJ) {
            int e = t / PROJ, j = t % PROJ;
            int h = j >> 6, a = j & 63;
            g_Wc[t] = W1[(h * 512 + e) * 64 + a];
            continue;
        }
        t -= EMB * PROJ;
        if (t < EMB * PROJ) {
            int e = t / PROJ, j = t % PROJ;
            int h = j >> 6, a = j & 63;
            g_Wnb[t] = W1[(h * 512 + 256 + e) * 64 + a];
            continue;
        }
        t -= EMB * PROJ;
        if (t < NH * HDIM * HDIM) {
            int h = t / (HDIM * HDIM);
            int r = t % (HDIM * HDIM);
            int d = r / HDIM, e = r % HDIM;
            g_Wg[t] = gateW[h * HDIM * HDIM + e * HDIM + d];
            continue;
        }
        t -= NH * HDIM * HDIM;
        {
            int d = t / EMB, e = t % EMB;
            g_WoutT[t] = outW[e * EMB + d];
        }
    }
}

// ---------------- center gather ----------------
__global__ void gather_center_kernel(const int* __restrict__ cidx,
                                     const float* __restrict__ emb) {
    int b = blockIdx.x;
    int e = threadIdx.x;
    int c = cidx[b];
    float v = 0.f;
    if (c >= 0) v = emb[(size_t)c * EMB + e];
    g_C[(size_t)b * EMB + e] = v;
}

// ---------------- fp32 SGEMM: C[m, coff+n0+n] = sum_k A[m,k]*W[k,n0+n] (+bias) ----------------
// BM=BN=128, BK=16, 8x8 per thread, 256 threads.
__global__ void __launch_bounds__(256) sgemm_kernel(
    const float* __restrict__ A, int lda, int M, int Kd,
    const float* __restrict__ W, int ldw,
    float* __restrict__ C, int ldc, int coff,
    const float* __restrict__ bias,
    const int* __restrict__ cidx) {
    __shared__ float As[16][132];   // transposed A tile [k][m], padded
    __shared__ float Ws[16][128];   // W tile [k][n]

    int tid = threadIdx.x;
    int m0 = blockIdx.x * 128;
    int n0 = blockIdx.y * 128;
    int tr = tid >> 4;   // 0..15 -> row block
    int tc = tid & 15;   // 0..15 -> col block

    float acc[8][8];
#pragma unroll
    for (int i = 0; i < 8; i++)
#pragma unroll
        for (int j = 0; j < 8; j++) acc[i][j] = 0.f;

    int aRow = tid >> 2;          // 0..63
    int aCol = (tid & 3) * 4;     // 0,4,8,12
    int wRow = tid >> 5;          // 0..7
    int wCol = (tid & 31) * 4;    // 0..124

    for (int k0 = 0; k0 < Kd; k0 += 16) {
#pragma unroll
        for (int r = 0; r < 128; r += 64) {
            int m = m0 + aRow + r;
            float4 v = make_float4(0.f, 0.f, 0.f, 0.f);
            if (m < M) v = *(const float4*)(A + (size_t)m * lda + k0 + aCol);
            As[aCol + 0][aRow + r] = v.x;
            As[aCol + 1][aRow + r] = v.y;
            As[aCol + 2][aRow + r] = v.z;
            As[aCol + 3][aRow + r] = v.w;
        }
#pragma unroll
        for (int r = 0; r < 16; r += 8) {
            int kk = wRow + r;
            float4 v = *(const float4*)(W + (size_t)(k0 + kk) * ldw + n0 + wCol);
            *(float4*)&Ws[kk][wCol] = v;
        }
        __syncthreads();
#pragma unroll
        for (int kk = 0; kk < 16; kk++) {
            float rM[8], rN[8];
#pragma unroll
            for (int i = 0; i < 8; i++) rM[i] = As[kk][tr * 8 + i];
            *(float4*)&rN[0] = *(const float4*)&Ws[kk][tc * 8];
            *(float4*)&rN[4] = *(const float4*)&Ws[kk][tc * 8 + 4];
#pragma unroll
            for (int i = 0; i < 8; i++)
#pragma unroll
                for (int j = 0; j < 8; j++)
                    acc[i][j] = fmaf(rM[i], rN[j], acc[i][j]);
        }
        __syncthreads();
    }

#pragma unroll
    for (int i = 0; i < 8; i++) {
        int m = m0 + tr * 8 + i;
        if (m >= M) continue;
        bool zero = (cidx != nullptr) && (cidx[m] < 0);
        float* crow = C + (size_t)m * ldc + coff + n0 + tc * 8;
#pragma unroll
        for (int j = 0; j < 8; j += 4) {
            float4 v;
            if (zero) {
                v = make_float4(0.f, 0.f, 0.f, 0.f);
            } else {
                v.x = acc[i][j + 0];
                v.y = acc[i][j + 1];
                v.z = acc[i][j + 2];
                v.w = acc[i][j + 3];
                if (bias != nullptr) {
                    const float* bb = bias + n0 + tc * 8 + j;
                    v.x += bb[0]; v.y += bb[1]; v.z += bb[2]; v.w += bb[3];
                }
            }
            *(float4*)(crow + j) = v;
        }
    }
}

// ---------------- attention + aggregate + combine ----------------
__device__ __forceinline__ float gelu_f(float x) {
    return 0.5f * x * (1.0f + erff(x * 0.70710678118654752440f));
}

__global__ void __launch_bounds__(256) attn_kernel(
    const int* __restrict__ cidx,
    const float* __restrict__ emb,
    const int* __restrict__ nb_idx,
    const float* __restrict__ nb_wt,
    const float* __restrict__ W2,
    const float* __restrict__ b2) {
    __shared__ int s_idx[NK];
    __shared__ int s_msk[NK];
    __shared__ float s_lw[NK];
    __shared__ float s_cp[PROJ];
    __shared__ float s_w2[PROJ];
    __shared__ float s_logit[NH][NK];
    __shared__ float s_sw[NH][NK];

    int b = blockIdx.x;
    int tid = threadIdx.x;
    int c = cidx[b];
    int safe = (c > 0) ? c : 0;

    if (tid < NK) {
        int ni = nb_idx[(size_t)safe * NK + tid];
        s_idx[tid] = (ni > 0) ? ni : 0;
        s_msk[tid] = (ni >= 0) ? 1 : 0;
        s_lw[tid] = logf(nb_wt[(size_t)safe * NK + tid] + 1e-8f);
    }
    if (tid >= 128) {
        int j = tid - 128;
        s_cp[j] = g_CP[(size_t)b * PROJ + j];
        s_w2[j] = W2[j];
    }
    __syncthreads();

    // ---- phase 1: logits. 16 groups of 16 lanes, one group per neighbor k.
    int grp = tid >> 4;   // k
    int ln = tid & 15;
    const float* Pr = g_P + (size_t)s_idx[grp] * PROJ;
    float4 x0 = *(const float4*)(Pr + ln * 4);        // head 0
    float4 x1 = *(const float4*)(Pr + 64 + ln * 4);   // head 1
    float p0, p1;
    {
        int o = ln * 4;
        p0  = gelu_f(x0.x + s_cp[o + 0]) * s_w2[o + 0];
        p0 += gelu_f(x0.y + s_cp[o + 1]) * s_w2[o + 1];
        p0 += gelu_f(x0.z + s_cp[o + 2]) * s_w2[o + 2];
        p0 += gelu_f(x0.w + s_cp[o + 3]) * s_w2[o + 3];
        int o1 = 64 + ln * 4;
        p1  = gelu_f(x1.x + s_cp[o1 + 0]) * s_w2[o1 + 0];
        p1 += gelu_f(x1.y + s_cp[o1 + 1]) * s_w2[o1 + 1];
        p1 += gelu_f(x1.z + s_cp[o1 + 2]) * s_w2[o1 + 2];
        p1 += gelu_f(x1.w + s_cp[o1 + 3]) * s_w2[o1 + 3];
    }
#pragma unroll
    for (int off = 8; off > 0; off >>= 1) {
        p0 += __shfl_down_sync(0xffffffffu, p0, off, 16);
        p1 += __shfl_down_sync(0xffffffffu, p1, off, 16);
    }
    if (ln == 0) {
        float l0 = p0 + b2[0] + s_lw[grp];
        float l1 = p1 + b2[1] + s_lw[grp];
        if (!s_msk[grp]) { l0 = -1e30f; l1 = -1e30f; }
        s_logit[0][grp] = l0;
        s_logit[1][grp] = l1;
    }
    __syncthreads();

    // ---- phase 2: softmax over k (32 lanes: [h=0|k 0..15][h=1|k 0..15])
    if (tid < 32) {
        int h = tid >> 4, k = tid & 15;
        int any = 0;
#pragma unroll
        for (int i = 0; i < NK; i++) any |= s_msk[i];
        float l = s_logit[h][k];
        if (!any) l = 0.f;
        float m = l;
#pragma unroll
        for (int off = 8; off > 0; off >>= 1)
            m = fmaxf(m, __shfl_xor_sync(0xffffffffu, m, off, 16));
        float e = expf(l - m);
        float s = e;
#pragma unroll
        for (int off = 8; off > 0; off >>= 1)
            s += __shfl_xor_sync(0xffffffffu, s, off, 16);
        s_sw[h][k] = e / s;
    }
    __syncthreads();

    // ---- phase 3: weighted aggregate + gate + combine. thread = output dim e.
    {
        int h = tid >> 7;
        float acc = 0.f;
#pragma unroll
        for (int k = 0; k < NK; k++)
            acc += s_sw[h][k] * emb[(size_t)s_idx[k] * EMB + tid];
        size_t o = (size_t)b * EMB + tid;
        float gate = 1.f / (1.f + expf(-g_G[o]));
        g_comb[o] = g_C[o] + gate * acc;
    }
}

// ---------------- launcher ----------------
extern "C" void kernel_launch(void* const* d_in, const int* in_sizes, int n_in,
                              void* d_out, int out_size) {
    const int*   cidx  = (const int*)d_in[0];
    const float* emb   = (const float*)d_in[1];
    const int*   nbidx = (const int*)d_in[2];
    const float* nbwt  = (const float*)d_in[3];
    const float* W1    = (const float*)d_in[4];
    const float* b1    = (const float*)d_in[5];
    const float* W2    = (const float*)d_in[6];
    const float* b2    = (const float*)d_in[7];
    const float* gW    = (const float*)d_in[8];
    const float* gb    = (const float*)d_in[9];
    const float* oW    = (const float*)d_in[10];
    const float* ob    = (const float*)d_in[11];
    float* out = (float*)d_out;

    static float *pP = nullptr, *pC = nullptr, *pCP = nullptr, *pG = nullptr,
                 *pComb = nullptr, *pWc = nullptr, *pWnb = nullptr,
                 *pWg = nullptr, *pWoutT = nullptr;
    if (pP == nullptr) {
        cudaGetSymbolAddress((void**)&pP, g_P);
        cudaGetSymbolAddress((void**)&pC, g_C);
        cudaGetSymbolAddress((void**)&pCP, g_CP);
        cudaGetSymbolAddress((void**)&pG, g_G);
        cudaGetSymbolAddress((void**)&pComb, g_comb);
        cudaGetSymbolAddress((void**)&pWc, g_Wc);
        cudaGetSymbolAddress((void**)&pWnb, g_Wnb);
        cudaGetSymbolAddress((void**)&pWg, g_Wg);
        cudaGetSymbolAddress((void**)&pWoutT, g_WoutT);
    }

    // 1) repack weights
    prepack_kernel<<<160, 256>>>(W1, gW, oW);
    // 2) gather center embeddings (zeroed for invalid)
    gather_center_kernel<<<BATCH, 256>>>(cidx, emb);
    // 3) P = emb_table @ W1_nb   [200000 x 128]   (dominant GEMM)
    sgemm_kernel<<<dim3((NNODES + 127) / 128, 1), 256>>>(
        emb, EMB, NNODES, EMB, pWnb, PROJ, pP, PROJ, 0, nullptr, nullptr);
    // 4) CP = C @ W1_c + b1      [16384 x 128]
    sgemm_kernel<<<dim3(BATCH / 128, 1), 256>>>(
        pC, EMB, BATCH, EMB, pWc, PROJ, pCP, PROJ, 0, b1, nullptr);
    // 5) gate pre-activations per head: G[:, h*128:] = C[:, h*128:] @ gate_W[h]^T + gate_b[h]
    for (int h = 0; h < NH; h++) {
        sgemm_kernel<<<dim3(BATCH / 128, 1), 256>>>(
            pC + h * HDIM, EMB, BATCH, HDIM, pWg + h * HDIM * HDIM, HDIM,
            pG, EMB, h * HDIM, gb + h * HDIM, nullptr);
    }
    // 6) attention logits + softmax + weighted aggregate + gate-combine
    attn_kernel<<<BATCH, 256>>>(cidx, emb, nbidx, nbwt, W2, b2);
    // 7) out = combined @ out_W^T + out_b, zero rows for invalid centers
    sgemm_kernel<<<dim3(BATCH / 128, 2), 256>>>(
        pComb, EMB, BATCH, EMB, pWoutT, EMB, out, EMB, 0, ob, cidx);
}

// round 12
// speedup vs baseline: 2.0810x; 2.0810x over previous
#include <cuda_runtime.h>
#include <cuda_bf16.h>
#include <cstdint>
#include <cstdio>
#include <math.h>

#define BATCH 16384
#define NNODES 200000
#define NK 16
#define EMB 256
#define NH 2
#define NA 64
#define HDIM 128
#define PROJ 128   // NH*NA

#define WS_PITCH 136            // bf16 elems per Ws row (128 + 8 pad)
#define AS_PITCH 72             // bf16 elems per As row (64 + 8 pad)
#define SMEM_WS_BYTES (256 * WS_PITCH * 2)                      // 69632
#define SMEM_TOTAL_BYTES (SMEM_WS_BYTES + 128 * AS_PITCH * 2)   // 88064

// ---------------- device scratch (static globals; no allocation) ----------------
__device__ __nv_bfloat16 g_Pb[(size_t)NNODES * PROJ];   // neighbor projections (bf16)
__device__ float g_C[(size_t)BATCH * EMB];              // gathered centers
__device__ float g_CP[(size_t)BATCH * PROJ];            // center projections (+b1)
__device__ float g_G[(size_t)BATCH * EMB];              // gate pre-activations
__device__ __nv_bfloat16 g_combH[(size_t)BATCH * EMB];  // combined hi (bf16)
__device__ __nv_bfloat16 g_combL[(size_t)BATCH * EMB];  // combined lo (bf16)
__device__ __nv_bfloat16 g_Wcb[EMB * PROJ];             // W1 center half  [e][h*64+a]
__device__ __nv_bfloat16 g_Wnbb[EMB * PROJ];            // W1 neighbor half
__device__ __nv_bfloat16 g_Wgb[NH * HDIM * HDIM];       // gate_W^T per head [h][d][e]
__device__ __nv_bfloat16 g_WoTh[EMB * EMB];             // out_W^T hi  [d][e]
__device__ __nv_bfloat16 g_WoTl[EMB * EMB];             // out_W^T lo

// ---------------- weight repacking ----------------
__global__ void prepack_kernel(const float* __restrict__ W1,
                               const float* __restrict__ gateW,
                               const float* __restrict__ outW) {
    const int S1 = EMB * PROJ;
    const int S3 = NH * HDIM * HDIM;
    const int S4 = EMB * EMB;
    int total = 2 * S1 + S3 + S4;
    for (int i = blockIdx.x * blockDim.x + threadIdx.x; i < total;
         i += gridDim.x * blockDim.x) {
        int t = i;
        if (t < S1) {
            int e = t / PROJ, j = t % PROJ, h = j >> 6, a = j & 63;
            g_Wcb[t] = __float2bfloat16(W1[(h * 512 + e) * 64 + a]);
            continue;
        }
        t -= S1;
        if (t < S1) {
            int e = t / PROJ, j = t % PROJ, h = j >> 6, a = j & 63;
            g_Wnbb[t] = __float2bfloat16(W1[(h * 512 + 256 + e) * 64 + a]);
            continue;
        }
        t -= S1;
        if (t < S3) {
            int h = t / (HDIM * HDIM), r = t % (HDIM * HDIM);
            int d = r / HDIM, e = r % HDIM;
            g_Wgb[t] = __float2bfloat16(gateW[h * HDIM * HDIM + e * HDIM + d]);
            continue;
        }
        t -= S3;
        {
            int d = t / EMB, e = t % EMB;
            float v = outW[e * EMB + d];
            __nv_bfloat16 hi = __float2bfloat16(v);
            g_WoTh[t] = hi;
            g_WoTl[t] = __float2bfloat16(v - __bfloat162float(hi));
        }
    }
}

// ---------------- center gather ----------------
__global__ void gather_center_kernel(const int* __restrict__ cidx,
                                     const float* __restrict__ emb) {
    int b = blockIdx.x;
    int e = threadIdx.x;
    int c = cidx[b];
    float v = 0.f;
    if (c >= 0) v = emb[(size_t)c * EMB + e];
    g_C[(size_t)b * EMB + e] = v;
}

// ---------------- mma helpers ----------------
__device__ __forceinline__ void ldmat_x4(unsigned* r, const void* p) {
    unsigned addr = (unsigned)__cvta_generic_to_shared(p);
    asm volatile("ldmatrix.sync.aligned.m8n8.x4.shared.b16 {%0,%1,%2,%3}, [%4];"
                 : "=r"(r[0]), "=r"(r[1]), "=r"(r[2]), "=r"(r[3]) : "r"(addr));
}
__device__ __forceinline__ void ldmat_x4_t(unsigned* r, const void* p) {
    unsigned addr = (unsigned)__cvta_generic_to_shared(p);
    asm volatile("ldmatrix.sync.aligned.m8n8.x4.trans.shared.b16 {%0,%1,%2,%3}, [%4];"
                 : "=r"(r[0]), "=r"(r[1]), "=r"(r[2]), "=r"(r[3]) : "r"(addr));
}
__device__ __forceinline__ void mma_bf16(float* c, const unsigned* a, const unsigned* b) {
    asm volatile(
        "mma.sync.aligned.m16n8k16.row.col.f32.bf16.bf16.f32 "
        "{%0,%1,%2,%3}, {%4,%5,%6,%7}, {%8,%9}, {%0,%1,%2,%3};"
        : "+f"(c[0]), "+f"(c[1]), "+f"(c[2]), "+f"(c[3])
        : "r"(a[0]), "r"(a[1]), "r"(a[2]), "r"(a[3]), "r"(b[0]), "r"(b[1]));
}

// ---------------- bf16 tensor-core GEMM ----------------
// C[m, coff+n0+n] = sum over segments of A_seg[m, :K] @ W_seg[:K, n0+n] (+bias)
// Modes:
//   Af != null          : A is fp32, converted to bf16 in-tile, 1 segment
//   Af == null, nseg=3  : split mode: Ah@W0 + Ah@W1 + Al@W0  (fp32-quality product)
// Tiles: BM=128, BN=128, 8 warps (4x2), warp tile 32x64, mma.m16n8k16.
__global__ void __launch_bounds__(256, 2) mma_gemm_kernel(
    const float* __restrict__ Af,
    const __nv_bfloat16* __restrict__ Ah,
    const __nv_bfloat16* __restrict__ Al,
    int lda, int M, int K,
    const __nv_bfloat16* __restrict__ W0,
    const __nv_bfloat16* __restrict__ W1w, int ldw,
    float* __restrict__ Cf, __nv_bfloat16* __restrict__ Cb,
    int ldc, int coff,
    const float* __restrict__ bias,
    const int* __restrict__ cidx, int nseg) {
    extern __shared__ __align__(16) unsigned char smem[];
    __nv_bfloat16* Ws = (__nv_bfloat16*)smem;                   // [K<=256][WS_PITCH]
    __nv_bfloat16* As = (__nv_bfloat16*)(smem + SMEM_WS_BYTES); // [128][AS_PITCH]

    const int tid = threadIdx.x;
    const int lane = tid & 31, warp = tid >> 5;
    const int m0 = blockIdx.x * 128, n0 = blockIdx.y * 128;
    const int wm = (warp >> 1) * 32, wn = (warp & 1) * 64;

    float acc[2][8][4];
#pragma unroll
    for (int mi = 0; mi < 2; mi++)
#pragma unroll
        for (int nj = 0; nj < 8; nj++)
#pragma unroll
            for (int q = 0; q < 4; q++) acc[mi][nj][q] = 0.f;

    for (int s = 0; s < nseg; s++) {
        // select W for this segment: s0 -> W0, s1 -> W1w, s2 -> W0 again
        const __nv_bfloat16* Wsrc = (s == 1) ? W1w : W0;
        if (s > 0) __syncthreads();   // all warps done with previous Ws contents
        // load W slice [K][128] into smem: 128 bf16 per row = 16 uint4
        for (int k = tid; k < K; k += 256) {
            const uint4* src = (const uint4*)(Wsrc + (size_t)k * ldw + n0);
            uint4* dst = (uint4*)(Ws + k * WS_PITCH);
#pragma unroll
            for (int j = 0; j < 16; j++) dst[j] = src[j];
        }
        const __nv_bfloat16* Asb = (s == 2) ? Al : Ah;

        for (int k0 = 0; k0 < K; k0 += 64) {
            // ---- load A chunk [128][64] into As ----
            if (Af != nullptr) {
                int rb = tid >> 4, c4 = (tid & 15) * 4;
#pragma unroll
                for (int r = 0; r < 8; r++) {
                    int row = rb + r * 16;
                    int m = m0 + row;
                    float4 v = make_float4(0.f, 0.f, 0.f, 0.f);
                    if (m < M) v = *(const float4*)(Af + (size_t)m * lda + k0 + c4);
                    __nv_bfloat162* d2 = (__nv_bfloat162*)(As + row * AS_PITCH + c4);
                    d2[0] = __floats2bfloat162_rn(v.x, v.y);
                    d2[1] = __floats2bfloat162_rn(v.z, v.w);
                }
            } else {
                // 8 threads per row, each one uint4 (8 bf16): full 64-elem coverage
#pragma unroll
                for (int r = 0; r < 4; r++) {
                    int row = (tid >> 3) + r * 32;
                    int m = m0 + row;
                    uint4 v = make_uint4(0u, 0u, 0u, 0u);
                    if (m < M)
                        v = *(const uint4*)(Asb + (size_t)m * lda + k0 + (tid & 7) * 8);
                    *(uint4*)(As + row * AS_PITCH + (tid & 7) * 8) = v;
                }
            }
            __syncthreads();
            // ---- compute 4 k16 steps ----
#pragma unroll
            for (int kk = 0; kk < 4; kk++) {
                unsigned a[2][4];
#pragma unroll
                for (int mi = 0; mi < 2; mi++)
                    ldmat_x4(a[mi], As + (wm + mi * 16 + (lane & 15)) * AS_PITCH +
                                        kk * 16 + (lane >> 4) * 8);
                unsigned b[8][2];
#pragma unroll
                for (int p = 0; p < 4; p++) {
                    unsigned r[4];
                    ldmat_x4_t(r, Ws + (k0 + kk * 16 + (lane & 15)) * WS_PITCH +
                                      wn + p * 16 + (lane >> 4) * 8);
                    b[2 * p][0] = r[0]; b[2 * p][1] = r[1];
                    b[2 * p + 1][0] = r[2]; b[2 * p + 1][1] = r[3];
                }
#pragma unroll
                for (int mi = 0; mi < 2; mi++)
#pragma unroll
                    for (int nj = 0; nj < 8; nj++)
                        mma_bf16(acc[mi][nj], a[mi], b[nj]);
            }
            __syncthreads();
        }
    }

    // ---- store ----
    int group = lane >> 2, tig = lane & 3;
#pragma unroll
    for (int mi = 0; mi < 2; mi++) {
#pragma unroll
        for (int half = 0; half < 2; half++) {
            int m = m0 + wm + mi * 16 + group + half * 8;
            if (m >= M) continue;
            bool zero = (cidx != nullptr) && (cidx[m] < 0);
#pragma unroll
            for (int nj = 0; nj < 8; nj++) {
                int colb = wn + nj * 8 + 2 * tig;
                float v0 = acc[mi][nj][half * 2 + 0];
                float v1 = acc[mi][nj][half * 2 + 1];
                if (bias != nullptr) {
                    v0 += bias[n0 + colb];
                    v1 += bias[n0 + colb + 1];
                }
                if (zero) { v0 = 0.f; v1 = 0.f; }
                size_t off = (size_t)m * ldc + coff + n0 + colb;
                if (Cf != nullptr) {
                    *(float2*)(Cf + off) = make_float2(v0, v1);
                } else {
                    *(__nv_bfloat162*)(Cb + off) = __floats2bfloat162_rn(v0, v1);
                }
            }
        }
    }
}

// ---------------- attention + aggregate + combine ----------------
__device__ __forceinline__ float gelu_f(float x) {
    return 0.5f * x * (1.0f + erff(x * 0.70710678118654752440f));
}

__global__ void __launch_bounds__(256) attn_kernel(
    const int* __restrict__ cidx,
    const float* __restrict__ emb,
    const int* __restrict__ nb_idx,
    const float* __restrict__ nb_wt,
    const float* __restrict__ W2,
    const float* __restrict__ b2) {
    __shared__ int s_idx[NK];
    __shared__ int s_msk[NK];
    __shared__ float s_lw[NK];
    __shared__ float s_cp[PROJ];
    __shared__ float s_w2[PROJ];
    __shared__ float s_logit[NH][NK];
    __shared__ float s_sw[NH][NK];

    int b = blockIdx.x;
    int tid = threadIdx.x;
    int c = cidx[b];
    int safe = (c > 0) ? c : 0;

    if (tid < NK) {
        int ni = nb_idx[(size_t)safe * NK + tid];
        s_idx[tid] = (ni > 0) ? ni : 0;
        s_msk[tid] = (ni >= 0) ? 1 : 0;
        s_lw[tid] = logf(nb_wt[(size_t)safe * NK + tid] + 1e-8f);
    }
    if (tid >= 128) {
        int j = tid - 128;
        s_cp[j] = g_CP[(size_t)b * PROJ + j];
        s_w2[j] = W2[j];
    }
    __syncthreads();

    // ---- phase 1: logits. 16 groups of 16 lanes, one group per neighbor k.
    int grp = tid >> 4;
    int ln = tid & 15;
    const __nv_bfloat16* Pr = g_Pb + (size_t)s_idx[grp] * PROJ;
    __nv_bfloat162 q0a = *(const __nv_bfloat162*)(Pr + ln * 4);
    __nv_bfloat162 q0b = *(const __nv_bfloat162*)(Pr + ln * 4 + 2);
    __nv_bfloat162 q1a = *(const __nv_bfloat162*)(Pr + 64 + ln * 4);
    __nv_bfloat162 q1b = *(const __nv_bfloat162*)(Pr + 64 + ln * 4 + 2);
    float p0, p1;
    {
        int o = ln * 4;
        p0  = gelu_f(__bfloat162float(q0a.x) + s_cp[o + 0]) * s_w2[o + 0];
        p0 += gelu_f(__bfloat162float(q0a.y) + s_cp[o + 1]) * s_w2[o + 1];
        p0 += gelu_f(__bfloat162float(q0b.x) + s_cp[o + 2]) * s_w2[o + 2];
        p0 += gelu_f(__bfloat162float(q0b.y) + s_cp[o + 3]) * s_w2[o + 3];
        int o1 = 64 + ln * 4;
        p1  = gelu_f(__bfloat162float(q1a.x) + s_cp[o1 + 0]) * s_w2[o1 + 0];
        p1 += gelu_f(__bfloat162float(q1a.y) + s_cp[o1 + 1]) * s_w2[o1 + 1];
        p1 += gelu_f(__bfloat162float(q1b.x) + s_cp[o1 + 2]) * s_w2[o1 + 2];
        p1 += gelu_f(__bfloat162float(q1b.y) + s_cp[o1 + 3]) * s_w2[o1 + 3];
    }
#pragma unroll
    for (int off = 8; off > 0; off >>= 1) {
        p0 += __shfl_down_sync(0xffffffffu, p0, off, 16);
        p1 += __shfl_down_sync(0xffffffffu, p1, off, 16);
    }
    if (ln == 0) {
        float l0 = p0 + b2[0] + s_lw[grp];
        float l1 = p1 + b2[1] + s_lw[grp];
        if (!s_msk[grp]) { l0 = -1e30f; l1 = -1e30f; }
        s_logit[0][grp] = l0;
        s_logit[1][grp] = l1;
    }
    __syncthreads();

    // ---- phase 2: softmax over k
    if (tid < 32) {
        int h = tid >> 4, k = tid & 15;
        int any = 0;
#pragma unroll
        for (int i = 0; i < NK; i++) any |= s_msk[i];
        float l = s_logit[h][k];
        if (!any) l = 0.f;
        float m = l;
#pragma unroll
        for (int off = 8; off > 0; off >>= 1)
            m = fmaxf(m, __shfl_xor_sync(0xffffffffu, m, off, 16));
        float e = expf(l - m);
        float s = e;
#pragma unroll
        for (int off = 8; off > 0; off >>= 1)
            s += __shfl_xor_sync(0xffffffffu, s, off, 16);
        s_sw[h][k] = e / s;
    }
    __syncthreads();

    // ---- phase 3: weighted aggregate + gate + combine (hi/lo bf16 split out)
    {
        int h = tid >> 7;
        float acc = 0.f;
#pragma unroll
        for (int k = 0; k < NK; k++)
            acc += s_sw[h][k] * emb[(size_t)s_idx[k] * EMB + tid];
        size_t o = (size_t)b * EMB + tid;
        float gate = 1.f / (1.f + expf(-g_G[o]));
        float v = g_C[o] + gate * acc;
        __nv_bfloat16 hi = __float2bfloat16(v);
        g_combH[o] = hi;
        g_combL[o] = __float2bfloat16(v - __bfloat162float(hi));
    }
}

// ---------------- launcher ----------------
extern "C" void kernel_launch(void* const* d_in, const int* in_sizes, int n_in,
                              void* d_out, int out_size) {
    const int*   cidx  = (const int*)d_in[0];
    const float* emb   = (const float*)d_in[1];
    const int*   nbidx = (const int*)d_in[2];
    const float* nbwt  = (const float*)d_in[3];
    const float* W1    = (const float*)d_in[4];
    const float* b1    = (const float*)d_in[5];
    const float* W2    = (const float*)d_in[6];
    const float* b2    = (const float*)d_in[7];
    const float* gW    = (const float*)d_in[8];
    const float* gb    = (const float*)d_in[9];
    const float* oW    = (const float*)d_in[10];
    const float* ob    = (const float*)d_in[11];
    float* out = (float*)d_out;

    static float* pC = 0;
    static float* pCP = 0;
    static float* pG = 0;
    static __nv_bfloat16* pPb = 0;
    static __nv_bfloat16* pCombH = 0;
    static __nv_bfloat16* pCombL = 0;
    static __nv_bfloat16* pWcb = 0;
    static __nv_bfloat16* pWnbb = 0;
    static __nv_bfloat16* pWgb = 0;
    static __nv_bfloat16* pWoTh = 0;
    static __nv_bfloat16* pWoTl = 0;
    if (pC == 0) {
        cudaGetSymbolAddress((void**)&pC, g_C);
        cudaGetSymbolAddress((void**)&pCP, g_CP);
        cudaGetSymbolAddress((void**)&pG, g_G);
        cudaGetSymbolAddress((void**)&pPb, g_Pb);
        cudaGetSymbolAddress((void**)&pCombH, g_combH);
        cudaGetSymbolAddress((void**)&pCombL, g_combL);
        cudaGetSymbolAddress((void**)&pWcb, g_Wcb);
        cudaGetSymbolAddress((void**)&pWnbb, g_Wnbb);
        cudaGetSymbolAddress((void**)&pWgb, g_Wgb);
        cudaGetSymbolAddress((void**)&pWoTh, g_WoTh);
        cudaGetSymbolAddress((void**)&pWoTl, g_WoTl);
        cudaFuncSetAttribute(mma_gemm_kernel,
                             cudaFuncAttributeMaxDynamicSharedMemorySize,
                             SMEM_TOTAL_BYTES);
    }

    // 1) repack weights (bf16 + hi/lo split for out_W)
    prepack_kernel<<<160, 256>>>(W1, gW, oW);
    // 2) gather center embeddings
    gather_center_kernel<<<BATCH, 256>>>(cidx, emb);
    // 3) P = emb_table @ W1_nb  -> bf16  [200000 x 128]
    mma_gemm_kernel<<<dim3((NNODES + 127) / 128, 1), 256, SMEM_TOTAL_BYTES>>>(
        emb, (const __nv_bfloat16*)0, (const __nv_bfloat16*)0, EMB, NNODES, EMB,
        pWnbb, (const __nv_bfloat16*)0, PROJ,
        (float*)0, pPb, PROJ, 0, (const float*)0, (const int*)0, 1);
    // 4) CP = C @ W1_c + b1  -> fp32  [16384 x 128]
    mma_gemm_kernel<<<dim3(BATCH / 128, 1), 256, SMEM_TOTAL_BYTES>>>(
        pC, (const __nv_bfloat16*)0, (const __nv_bfloat16*)0, EMB, BATCH, EMB,
        pWcb, (const __nv_bfloat16*)0, PROJ,
        pCP, (__nv_bfloat16*)0, PROJ, 0, b1, (const int*)0, 1);
    // 5) gate pre-activations per head
    for (int h = 0; h < NH; h++) {
        mma_gemm_kernel<<<dim3(BATCH / 128, 1), 256, SMEM_TOTAL_BYTES>>>(
            pC + h * HDIM, (const __nv_bfloat16*)0, (const __nv_bfloat16*)0,
            EMB, BATCH, HDIM,
            pWgb + h * HDIM * HDIM, (const __nv_bfloat16*)0, HDIM,
            pG, (__nv_bfloat16*)0, EMB, h * HDIM, gb + h * HDIM, (const int*)0, 1);
    }
    // 6) attention logits + softmax + aggregate + gate-combine (emits hi/lo bf16)
    attn_kernel<<<BATCH, 256>>>(cidx, emb, nbidx, nbwt, W2, b2);
    // 7) out = comb @ out_W^T + out_b via split-bf16 (hi*hi + hi*lo + lo*hi)
    mma_gemm_kernel<<<dim3(BATCH / 128, 2), 256, SMEM_TOTAL_BYTES>>>(
        (const float*)0, pCombH, pCombL, EMB, BATCH, EMB,
        pWoTh, pWoTl, EMB, out, (__nv_bfloat16*)0, EMB, 0, ob, cidx, 3);
}

// round 15
// speedup vs baseline: 2.3749x; 1.1413x over previous
#include <cuda_runtime.h>
#include <cuda_bf16.h>
#include <cstdint>
#include <math.h>

#define BATCH 16384
#define NNODES 200000
#define NK 16
#define EMB 256
#define NH 2
#define NA 64
#define HDIM 128
#define PROJ 128   // NH*NA
#define NBIG 384   // fused CP(128) + gate(256) output width

#define WS_PITCH 136                         // bf16 per Ws row (128+8)
#define WS_BYTES (256 * WS_PITCH * 2)        // 69632
#define SF_PITCH 36                          // fp32 stage pitch (32+4)
#define SB_PITCH 40                          // bf16 stage pitch (32+8)
#define SF_BUF (128 * SF_PITCH)              // floats per stage buffer
#define SB_BUF (128 * SB_PITCH)              // bf16 per stage buffer
#define STAGE_BYTES (2 * SF_BUF * 4)         // 36864 (fp32 stage is the larger union member)
#define SMEM_TOTAL (WS_BYTES + STAGE_BYTES)  // 106496

// ---------------- device scratch (static globals; no allocation) ----------------
__device__ __align__(16) __nv_bfloat16 g_Pb[(size_t)NNODES * PROJ];   // neighbor projections
__device__ __align__(16) float g_C[(size_t)BATCH * EMB];              // gathered centers
__device__ __align__(16) float g_CPG[(size_t)BATCH * NBIG];           // [CP | gate-preact]
__device__ __align__(16) __nv_bfloat16 g_combH[(size_t)BATCH * EMB];  // combined hi
__device__ __align__(16) __nv_bfloat16 g_combL[(size_t)BATCH * EMB];  // combined lo
__device__ __align__(16) __nv_bfloat16 g_Wnbb[EMB * PROJ];            // W1 neighbor half [e][h*64+a]
__device__ __align__(16) __nv_bfloat16 g_Wbig[EMB * NBIG];            // [Wc | blockdiag gate^T]
__device__ __align__(16) float g_biasBig[NBIG];
__device__ __align__(16) __nv_bfloat16 g_WoTh[EMB * EMB];             // out_W^T hi
__device__ __align__(16) __nv_bfloat16 g_WoTl[EMB * EMB];             // out_W^T lo

// ---------------- weight repacking ----------------
__global__ void prepack_kernel(const float* __restrict__ W1,
                               const float* __restrict__ gateW,
                               const float* __restrict__ b1,
                               const float* __restrict__ gb,
                               const float* __restrict__ outW) {
    const int Snb = EMB * PROJ;          // 32768
    const int Sbig = EMB * NBIG;         // 98304
    const int Sout = EMB * EMB;          // 65536
    int total = Snb + Sbig + Sout + NBIG;
    for (int i = blockIdx.x * blockDim.x + threadIdx.x; i < total;
         i += gridDim.x * blockDim.x) {
        int t = i;
        if (t < Snb) {
            int e = t / PROJ, j = t % PROJ, h = j >> 6, a = j & 63;
            g_Wnbb[t] = __float2bfloat16(W1[(h * 512 + 256 + e) * 64 + a]);
            continue;
        }
        t -= Snb;
        if (t < Sbig) {
            int k = t / NBIG, col = t % NBIG;
            float v;
            if (col < 128) {
                int h = col >> 6, a = col & 63;
                v = W1[(h * 512 + k) * 64 + a];
            } else {
                int j2 = col - 128;
                int h = j2 >> 7, e = j2 & 127;
                v = ((k >> 7) == h) ? gateW[h * HDIM * HDIM + e * HDIM + (k & 127)]
                                    : 0.f;
            }
            g_Wbig[t] = __float2bfloat16(v);
            continue;
        }
        t -= Sbig;
        if (t < Sout) {
            int d = t / EMB, e = t % EMB;
            float v = outW[e * EMB + d];
            __nv_bfloat16 hi = __float2bfloat16(v);
            g_WoTh[t] = hi;
            g_WoTl[t] = __float2bfloat16(v - __bfloat162float(hi));
            continue;
        }
        t -= Sout;
        g_biasBig[t] = (t < 128) ? b1[t] : gb[t - 128];
    }
}

// ---------------- center gather (fp32 centers for attn) ----------------
__global__ void gather_center_kernel(const int* __restrict__ cidx,
                                     const float* __restrict__ emb) {
    int b = blockIdx.x;
    int e = threadIdx.x;
    int c = cidx[b];
    float v = 0.f;
    if (c >= 0) v = emb[(size_t)c * EMB + e];
    g_C[(size_t)b * EMB + e] = v;
}

// ---------------- helpers ----------------
__device__ __forceinline__ void cpasync16(void* dst, const void* src, int bytes) {
    unsigned d = (unsigned)__cvta_generic_to_shared(dst);
    asm volatile("cp.async.ca.shared.global [%0], [%1], 16, %2;"
                 :: "r"(d), "l"(src), "r"(bytes));
}
#define CP_COMMIT() asm volatile("cp.async.commit_group;")
#define CP_WAIT0()  asm volatile("cp.async.wait_group 0;")

__device__ __forceinline__ void ldmat_x4(unsigned* r, const void* p) {
    unsigned addr = (unsigned)__cvta_generic_to_shared(p);
    asm volatile("ldmatrix.sync.aligned.m8n8.x4.shared.b16 {%0,%1,%2,%3}, [%4];"
                 : "=r"(r[0]), "=r"(r[1]), "=r"(r[2]), "=r"(r[3]) : "r"(addr));
}
__device__ __forceinline__ void ldmat_x4_t(unsigned* r, const void* p) {
    unsigned addr = (unsigned)__cvta_generic_to_shared(p);
    asm volatile("ldmatrix.sync.aligned.m8n8.x4.trans.shared.b16 {%0,%1,%2,%3}, [%4];"
                 : "=r"(r[0]), "=r"(r[1]), "=r"(r[2]), "=r"(r[3]) : "r"(addr));
}
__device__ __forceinline__ void mma_bf16(float* c, const unsigned* a, const unsigned* b) {
    asm volatile(
        "mma.sync.aligned.m16n8k16.row.col.f32.bf16.bf16.f32 "
        "{%0,%1,%2,%3}, {%4,%5,%6,%7}, {%8,%9}, {%0,%1,%2,%3};"
        : "+f"(c[0]), "+f"(c[1]), "+f"(c[2]), "+f"(c[3])
        : "r"(a[0]), "r"(a[1]), "r"(a[2]), "r"(a[3]), "r"(b[0]), "r"(b[1]));
}
__device__ __forceinline__ unsigned pack2(float lo, float hi) {
    __nv_bfloat162 t = __floats2bfloat162_rn(lo, hi);
    return *(unsigned*)&t;
}

// ---------------- pipelined bf16 tensor-core GEMM ----------------
// C[m, coff+n0+n] = sum over segments of A_seg[m,:K] @ W_seg[:K, n0+n] (+bias)
//   Af != null : fp32 A (cp.async fp32 stage, cvt at fragment build), optional
//                ridx row-gather (neg -> zero row), 1 segment.
//   Af == null : bf16 A; nseg=3 split mode: Ah@W0 + Ah@W1 + Al@W0.
// BM=BN=128, k-chunk 32, double-buffered cp.async stage, 8 warps (4x2).
__global__ void __launch_bounds__(256, 2) gemm_kernel(
    const float* __restrict__ Af,
    const __nv_bfloat16* __restrict__ Ah,
    const __nv_bfloat16* __restrict__ Al,
    const int* __restrict__ ridx,
    int lda, int M, int K,
    const __nv_bfloat16* __restrict__ W0,
    const __nv_bfloat16* __restrict__ W1w, int ldw,
    float* __restrict__ Cf, __nv_bfloat16* __restrict__ Cb,
    int ldc, int coff,
    const float* __restrict__ bias,
    const int* __restrict__ cidx, int nseg) {
    extern __shared__ __align__(16) unsigned char smem[];
    __nv_bfloat16* Ws = (__nv_bfloat16*)smem;            // [K<=256][WS_PITCH]
    float* Sf = (float*)(smem + WS_BYTES);               // [2][128][SF_PITCH]
    __nv_bfloat16* Sb = (__nv_bfloat16*)(smem + WS_BYTES); // union: [2][128][SB_PITCH]

    const int tid = threadIdx.x;
    const int lane = tid & 31, warp = tid >> 5;
    const int m0 = blockIdx.x * 128, n0 = blockIdx.y * 128;
    const int wm = (warp >> 1) * 32, wn = (warp & 1) * 64;

    // ---- precompute per-thread A source bases (rows fixed across chunks) ----
    const float* fsrc[4]; int fbytes[4]; int fdst[4];
    const __nv_bfloat16* hsrcH[2]; const __nv_bfloat16* hsrcL[2];
    int hbytes[2]; int hdst[2];
    if (Af != nullptr) {
#pragma unroll
        for (int j = 0; j < 4; j++) {
            int idx = tid + j * 256;          // 0..1023 -> row=idx>>3, seg=idx&7
            int row = idx >> 3;
            int m = m0 + row;
            int src_row = 0, by = 0;
            if (m < M) {
                if (ridx != nullptr) {
                    int rv = ridx[m];
                    src_row = rv > 0 ? rv : 0;
                    by = (rv >= 0) ? 16 : 0;
                } else { src_row = m; by = 16; }
            }
            fsrc[j] = Af + (size_t)src_row * lda + (idx & 7) * 4;
            fbytes[j] = by;
            fdst[j] = row * SF_PITCH + (idx & 7) * 4;
        }
    } else {
#pragma unroll
        for (int j = 0; j < 2; j++) {
            int idx = tid + j * 256;          // 0..511 -> row=idx>>2, seg=idx&3
            int row = idx >> 2;
            int m = m0 + row;
            size_t off = (size_t)((m < M) ? m : 0) * lda + (idx & 3) * 8;
            hsrcH[j] = Ah + off;
            hsrcL[j] = (Al != nullptr) ? (Al + off) : (Ah + off);
            hbytes[j] = (m < M) ? 16 : 0;
            hdst[j] = row * SB_PITCH + (idx & 3) * 8;
        }
    }

    float acc[2][8][4];
#pragma unroll
    for (int mi = 0; mi < 2; mi++)
#pragma unroll
        for (int nj = 0; nj < 8; nj++)
#pragma unroll
            for (int q = 0; q < 4; q++) acc[mi][nj][q] = 0.f;

    auto issueA = [&](int s, int c, int buf) {
        int kc = c * 32;
        if (Af != nullptr) {
            float* D = Sf + buf * SF_BUF;
#pragma unroll
            for (int j = 0; j < 4; j++)
                cpasync16(D + fdst[j], fsrc[j] + kc, fbytes[j]);
        } else {
            __nv_bfloat16* D = Sb + buf * SB_BUF;
            bool useL = (s == 2);
#pragma unroll
            for (int j = 0; j < 2; j++)
                cpasync16(D + hdst[j], (useL ? hsrcL[j] : hsrcH[j]) + kc, hbytes[j]);
        }
    };

    const int nch = K / 32;
    for (int s = 0; s < nseg; s++) {
        const __nv_bfloat16* Wsrc = (s == 1) ? W1w : W0;
        if (s > 0) __syncthreads();   // previous segment done with Ws + stage
        // W slice [K][128] via cp.async (row = 256B = 16 x 16B)
        for (int i = tid; i < K * 16; i += 256) {
            int row = i >> 4, seg = i & 15;
            cpasync16(Ws + row * WS_PITCH + seg * 8,
                      Wsrc + (size_t)row * ldw + n0 + seg * 8, 16);
        }
        issueA(s, 0, 0);
        CP_COMMIT();
        CP_WAIT0();
        __syncthreads();

        for (int c = 0; c < nch; c++) {
            int cur = c & 1;
            if (c + 1 < nch) { issueA(s, c + 1, cur ^ 1); CP_COMMIT(); }
            // ---- compute 2 k16 steps from stage[cur] ----
#pragma unroll
            for (int kk = 0; kk < 2; kk++) {
                unsigned a[2][4];
                if (Af != nullptr) {
                    const float* S = Sf + cur * SF_BUF;
                    int g = lane >> 2, cc = kk * 16 + (lane & 3) * 2;
#pragma unroll
                    for (int mi = 0; mi < 2; mi++) {
                        int r = wm + mi * 16 + g;
                        float2 f0 = *(const float2*)(S + r * SF_PITCH + cc);
                        float2 f1 = *(const float2*)(S + (r + 8) * SF_PITCH + cc);
                        float2 f2 = *(const float2*)(S + r * SF_PITCH + cc + 8);
                        float2 f3 = *(const float2*)(S + (r + 8) * SF_PITCH + cc + 8);
                        a[mi][0] = pack2(f0.x, f0.y);
                        a[mi][1] = pack2(f1.x, f1.y);
                        a[mi][2] = pack2(f2.x, f2.y);
                        a[mi][3] = pack2(f3.x, f3.y);
                    }
                } else {
                    const __nv_bfloat16* S = Sb + cur * SB_BUF;
#pragma unroll
                    for (int mi = 0; mi < 2; mi++)
                        ldmat_x4(a[mi], S + (wm + mi * 16 + (lane & 15)) * SB_PITCH +
                                            kk * 16 + (lane >> 4) * 8);
                }
                unsigned b[8][2];
                int krow = c * 32 + kk * 16 + (lane & 15);
#pragma unroll
                for (int p = 0; p < 4; p++) {
                    unsigned r[4];
                    ldmat_x4_t(r, Ws + krow * WS_PITCH + wn + p * 16 + (lane >> 4) * 8);
                    b[2 * p][0] = r[0]; b[2 * p][1] = r[1];
                    b[2 * p + 1][0] = r[2]; b[2 * p + 1][1] = r[3];
                }
#pragma unroll
                for (int mi = 0; mi < 2; mi++)
#pragma unroll
                    for (int nj = 0; nj < 8; nj++)
                        mma_bf16(acc[mi][nj], a[mi], b[nj]);
            }
            if (c + 1 < nch) CP_WAIT0();
            __syncthreads();
        }
    }

    // ---- store ----
    int group = lane >> 2, tig = lane & 3;
#pragma unroll
    for (int mi = 0; mi < 2; mi++) {
#pragma unroll
        for (int half = 0; half < 2; half++) {
            int m = m0 + wm + mi * 16 + group + half * 8;
            if (m >= M) continue;
            bool zero = (cidx != nullptr) && (cidx[m] < 0);
#pragma unroll
            for (int nj = 0; nj < 8; nj++) {
                int colb = wn + nj * 8 + 2 * tig;
                float v0 = acc[mi][nj][half * 2 + 0];
                float v1 = acc[mi][nj][half * 2 + 1];
                if (bias != nullptr) {
                    v0 += bias[n0 + colb];
                    v1 += bias[n0 + colb + 1];
                }
                if (zero) { v0 = 0.f; v1 = 0.f; }
                size_t off = (size_t)m * ldc + coff + n0 + colb;
                if (Cf != nullptr) {
                    *(float2*)(Cf + off) = make_float2(v0, v1);
                } else {
                    *(__nv_bfloat162*)(Cb + off) = __floats2bfloat162_rn(v0, v1);
                }
            }
        }
    }
}

// ---------------- attention + aggregate + combine ----------------
__device__ __forceinline__ float gelu_f(float x) {
    return 0.5f * x * (1.0f + erff(x * 0.70710678118654752440f));
}

__global__ void __launch_bounds__(256) attn_kernel(
    const int* __restrict__ cidx,
    const float* __restrict__ emb,
    const int* __restrict__ nb_idx,
    const float* __restrict__ nb_wt,
    const float* __restrict__ W2,
    const float* __restrict__ b2) {
    __shared__ int s_idx[NK];
    __shared__ int s_msk[NK];
    __shared__ float s_lw[NK];
    __shared__ float s_cp[PROJ];
    __shared__ float s_w2[PROJ];
    __shared__ float s_logit[NH][NK];
    __shared__ float s_sw[NH][NK];

    int b = blockIdx.x;
    int tid = threadIdx.x;
    int c = cidx[b];
    int safe = (c > 0) ? c : 0;

    if (tid < NK) {
        int ni = nb_idx[(size_t)safe * NK + tid];
        s_idx[tid] = (ni > 0) ? ni : 0;
        s_msk[tid] = (ni >= 0) ? 1 : 0;
        s_lw[tid] = logf(nb_wt[(size_t)safe * NK + tid] + 1e-8f);
    }
    if (tid >= 128) {
        int j = tid - 128;
        s_cp[j] = g_CPG[(size_t)b * NBIG + j];
        s_w2[j] = W2[j];
    }
    __syncthreads();

    // ---- phase 1: logits (16 groups of 16 lanes, one group per neighbor)
    int grp = tid >> 4;
    int ln = tid & 15;
    const __nv_bfloat16* Pr = g_Pb + (size_t)s_idx[grp] * PROJ;
    __nv_bfloat162 q0a = *(const __nv_bfloat162*)(Pr + ln * 4);
    __nv_bfloat162 q0b = *(const __nv_bfloat162*)(Pr + ln * 4 + 2);
    __nv_bfloat162 q1a = *(const __nv_bfloat162*)(Pr + 64 + ln * 4);
    __nv_bfloat162 q1b = *(const __nv_bfloat162*)(Pr + 64 + ln * 4 + 2);
    float p0, p1;
    {
        int o = ln * 4;
        p0  = gelu_f(__bfloat162float(q0a.x) + s_cp[o + 0]) * s_w2[o + 0];
        p0 += gelu_f(__bfloat162float(q0a.y) + s_cp[o + 1]) * s_w2[o + 1];
        p0 += gelu_f(__bfloat162float(q0b.x) + s_cp[o + 2]) * s_w2[o + 2];
        p0 += gelu_f(__bfloat162float(q0b.y) + s_cp[o + 3]) * s_w2[o + 3];
        int o1 = 64 + ln * 4;
        p1  = gelu_f(__bfloat162float(q1a.x) + s_cp[o1 + 0]) * s_w2[o1 + 0];
        p1 += gelu_f(__bfloat162float(q1a.y) + s_cp[o1 + 1]) * s_w2[o1 + 1];
        p1 += gelu_f(__bfloat162float(q1b.x) + s_cp[o1 + 2]) * s_w2[o1 + 2];
        p1 += gelu_f(__bfloat162float(q1b.y) + s_cp[o1 + 3]) * s_w2[o1 + 3];
    }
#pragma unroll
    for (int off = 8; off > 0; off >>= 1) {
        p0 += __shfl_down_sync(0xffffffffu, p0, off, 16);
        p1 += __shfl_down_sync(0xffffffffu, p1, off, 16);
    }
    if (ln == 0) {
        float l0 = p0 + b2[0] + s_lw[grp];
        float l1 = p1 + b2[1] + s_lw[grp];
        if (!s_msk[grp]) { l0 = -1e30f; l1 = -1e30f; }
        s_logit[0][grp] = l0;
        s_logit[1][grp] = l1;
    }
    __syncthreads();

    // ---- phase 2: softmax over k
    if (tid < 32) {
        int h = tid >> 4, k = tid & 15;
        int any = 0;
#pragma unroll
        for (int i = 0; i < NK; i++) any |= s_msk[i];
        float l = s_logit[h][k];
        if (!any) l = 0.f;
        float m = l;
#pragma unroll
        for (int off = 8; off > 0; off >>= 1)
            m = fmaxf(m, __shfl_xor_sync(0xffffffffu, m, off, 16));
        float e = expf(l - m);
        float s = e;
#pragma unroll
        for (int off = 8; off > 0; off >>= 1)
            s += __shfl_xor_sync(0xffffffffu, s, off, 16);
        s_sw[h][k] = e / s;
    }
    __syncthreads();

    // ---- phase 3: weighted aggregate + gate + combine (hi/lo bf16 split out)
    {
        int h = tid >> 7;
        float acc = 0.f;
#pragma unroll
        for (int k = 0; k < NK; k++)
            acc += s_sw[h][k] * emb[(size_t)s_idx[k] * EMB + tid];
        size_t o = (size_t)b * EMB + tid;
        float gp = g_CPG[(size_t)b * NBIG + 128 + tid];
        float gate = 1.f / (1.f + expf(-gp));
        float v = g_C[o] + gate * acc;
        __nv_bfloat16 hi = __float2bfloat16(v);
        g_combH[o] = hi;
        g_combL[o] = __float2bfloat16(v - __bfloat162float(hi));
    }
}

// ---------------- launcher ----------------
extern "C" void kernel_launch(void* const* d_in, const int* in_sizes, int n_in,
                              void* d_out, int out_size) {
    const int*   cidx  = (const int*)d_in[0];
    const float* emb   = (const float*)d_in[1];
    const int*   nbidx = (const int*)d_in[2];
    const float* nbwt  = (const float*)d_in[3];
    const float* W1    = (const float*)d_in[4];
    const float* b1    = (const float*)d_in[5];
    const float* W2    = (const float*)d_in[6];
    const float* b2    = (const float*)d_in[7];
    const float* gW    = (const float*)d_in[8];
    const float* gb    = (const float*)d_in[9];
    const float* oW    = (const float*)d_in[10];
    const float* ob    = (const float*)d_in[11];
    float* out = (float*)d_out;

    static float* pCPG = 0;
    static float* pBiasBig = 0;
    static __nv_bfloat16* pPb = 0;
    static __nv_bfloat16* pCombH = 0;
    static __nv_bfloat16* pCombL = 0;
    static __nv_bfloat16* pWnbb = 0;
    static __nv_bfloat16* pWbig = 0;
    static __nv_bfloat16* pWoTh = 0;
    static __nv_bfloat16* pWoTl = 0;
    static cudaStream_t sA = 0;
    static cudaEvent_t eP = 0, eA = 0;
    if (pCPG == 0) {
        cudaGetSymbolAddress((void**)&pCPG, g_CPG);
        cudaGetSymbolAddress((void**)&pBiasBig, g_biasBig);
        cudaGetSymbolAddress((void**)&pPb, g_Pb);
        cudaGetSymbolAddress((void**)&pCombH, g_combH);
        cudaGetSymbolAddress((void**)&pCombL, g_combL);
        cudaGetSymbolAddress((void**)&pWnbb, g_Wnbb);
        cudaGetSymbolAddress((void**)&pWbig, g_Wbig);
        cudaGetSymbolAddress((void**)&pWoTh, g_WoTh);
        cudaGetSymbolAddress((void**)&pWoTl, g_WoTl);
        cudaFuncSetAttribute(gemm_kernel,
                             cudaFuncAttributeMaxDynamicSharedMemorySize,
                             SMEM_TOTAL);
        cudaStreamCreateWithFlags(&sA, cudaStreamNonBlocking);
        cudaEventCreateWithFlags(&eP, cudaEventDisableTiming);
        cudaEventCreateWithFlags(&eA, cudaEventDisableTiming);
    }

    // 1) repack weights
    prepack_kernel<<<160, 256>>>(W1, gW, b1, gb, oW);
    // fork: P-GEMM on side stream (depends only on prepack)
    cudaEventRecord(eP, 0);
    cudaStreamWaitEvent(sA, eP, 0);
    // 2) P = emb_table @ W1_nb -> bf16  [200000 x 128]   (side stream)
    gemm_kernel<<<dim3((NNODES + 127) / 128, 1), 256, SMEM_TOTAL, sA>>>(
        emb, (const __nv_bfloat16*)0, (const __nv_bfloat16*)0, (const int*)0,
        EMB, NNODES, EMB,
        pWnbb, (const __nv_bfloat16*)0, PROJ,
        (float*)0, pPb, PROJ, 0, (const float*)0, (const int*)0, 1);
    cudaEventRecord(eA, sA);
    // 3) center gather (main stream, parallel with P)
    gather_center_kernel<<<BATCH, 256>>>(cidx, emb);
    // 4) fused CP+gate: CPG = gather(emb,cidx) @ Wbig + biasBig  [16384 x 384]
    gemm_kernel<<<dim3(BATCH / 128, NBIG / 128), 256, SMEM_TOTAL>>>(
        emb, (const __nv_bfloat16*)0, (const __nv_bfloat16*)0, cidx,
        EMB, BATCH, EMB,
        pWbig, (const __nv_bfloat16*)0, NBIG,
        pCPG, (__nv_bfloat16*)0, NBIG, 0, pBiasBig, (const int*)0, 1);
    // join P before attention
    cudaStreamWaitEvent(0, eA, 0);
    // 5) attention logits + softmax + aggregate + gate-combine
    attn_kernel<<<BATCH, 256>>>(cidx, emb, nbidx, nbwt, W2, b2);
    // 6) out = comb @ out_W^T + out_b via split-bf16 (3 segments)
    gemm_kernel<<<dim3(BATCH / 128, 2), 256, SMEM_TOTAL>>>(
        (const float*)0, pCombH, pCombL, (const int*)0,
        EMB, BATCH, EMB,
        pWoTh, pWoTl, EMB,
        out, (__nv_bfloat16*)0, EMB, 0, ob, cidx, 3);
}